// round 17
// baseline (speedup 1.0000x reference)
#include <cuda_runtime.h>
#include <cuda_fp16.h>
#include <cstdint>

#define B_ 16
#define S_ 2048
#define D_ 128
#define SCALE_ 0.08838834764831845f  // 1/sqrt(128)

#define QLD_ 136   // halves per Q/K smem row (128 data + 8 pad)
#define CLD_ 132   // floats per staging row (128 data + 4 pad)
#define HLD_ 48    // halves per P smem row (32 data + 16 pad)
#define VLD_ 136   // words per Vs2 pair-row (128 data + 8 pad)

// Pre-packed operands
__device__ half     g_qh[(size_t)B_ * S_ * D_];           // 8 MB
__device__ half     g_kh[(size_t)B_ * S_ * D_];           // 8 MB
__device__ half     g_phalf[(size_t)B_ * S_ * S_];        // 128 MB, perm-packed P
__device__ uint32_t g_vpair[(size_t)B_ * (S_ / 2) * D_];  // 8 MB, half2 k-paired V

__device__ __forceinline__ uint32_t h2u(half2 h) {
    union { half2 h; uint32_t u; } cvt;
    cvt.h = h;
    return cvt.u;
}

__device__ __forceinline__ uint32_t smem_u32(const void* p) {
    uint32_t a;
    asm("{ .reg .u64 t; cvta.to.shared.u64 t, %1; cvt.u32.u64 %0, t; }" : "=r"(a) : "l"(p));
    return a;
}

// D += A*B, m16n8k16 f16 (f32 accum)
__device__ __forceinline__ void mma16(float* d, uint32_t a0, uint32_t a1, uint32_t a2,
                                      uint32_t a3, uint32_t b0, uint32_t b1) {
    asm volatile(
        "mma.sync.aligned.m16n8k16.row.col.f32.f16.f16.f32 "
        "{%0,%1,%2,%3}, {%4,%5,%6,%7}, {%8,%9}, {%0,%1,%2,%3};"
        : "+f"(d[0]), "+f"(d[1]), "+f"(d[2]), "+f"(d[3])
        : "r"(a0), "r"(a1), "r"(a2), "r"(a3), "r"(b0), "r"(b1));
}

#define LDSM4(r0, r1, r2, r3, a) \
    asm volatile("ldmatrix.sync.aligned.m8n8.x4.shared.b16 {%0,%1,%2,%3}, [%4];" \
                 : "=r"(r0), "=r"(r1), "=r"(r2), "=r"(r3) : "r"(a))

#define CPA16(dst, src) \
    asm volatile("cp.async.cg.shared.global [%0], [%1], 16;" :: "r"(dst), "l"(src))
#define CP_COMMIT() asm volatile("cp.async.commit_group;" ::: "memory")
#define CP_WAIT1()  asm volatile("cp.async.wait_group 1;" ::: "memory")

// Permuted half store: within each 16-k group, k=2c+h+8e -> pos 4c+2e+h.
__device__ __forceinline__ void store_perm(half* rowp, int c4, float4 v) {
    const int kk0 = c4 & 15;
    const int pos = ((c4 >> 4) << 4) + ((kk0 & 7) << 1) + ((kk0 >> 3) << 1);
    *(half2*)(rowp + pos)     = __floats2half2_rn(v.x, v.y);
    *(half2*)(rowp + pos + 4) = __floats2half2_rn(v.z, v.w);
}

// =====================================================================
// Kernel 0a: f32 -> half row-major prepack (Q and K). 8 floats/thread.
// =====================================================================
__global__ __launch_bounds__(256) void hprep_kernel(const float* __restrict__ src,
                                                    half* __restrict__ dst)
{
    const size_t i = ((size_t)blockIdx.x * 256 + threadIdx.x) * 8;
    const float4 a = *(const float4*)&src[i];
    const float4 b = *(const float4*)&src[i + 4];
    uint4 u;
    u.x = h2u(__floats2half2_rn(a.x, a.y));
    u.y = h2u(__floats2half2_rn(a.z, a.w));
    u.z = h2u(__floats2half2_rn(b.x, b.y));
    u.w = h2u(__floats2half2_rn(b.z, b.w));
    *(uint4*)&dst[i] = u;
}

// =====================================================================
// Kernel 0b: pre-pack V -> half2 k-pairs (round-16 exact).
// =====================================================================
__global__ __launch_bounds__(256) void vprep_kernel(const float* __restrict__ v)
{
    const int idx = blockIdx.x * 256 + threadIdx.x;
    const int d4 = (idx & 31) * 4;
    const int p  = (idx >> 5) & 1023;
    const int b  = idx >> 15;
    const float* r0 = v + ((size_t)b * S_ + 2 * p) * D_ + d4;
    const float* r1 = r0 + D_;
    const float4 a = *(const float4*)r0;
    const float4 c = *(const float4*)r1;
    uint4 u;
    u.x = h2u(__floats2half2_rn(a.x, c.x));
    u.y = h2u(__floats2half2_rn(a.y, c.y));
    u.z = h2u(__floats2half2_rn(a.z, c.z));
    u.w = h2u(__floats2half2_rn(a.w, c.w));
    *(uint4*)&g_vpair[((size_t)b * (S_ / 2) + p) * D_ + d4] = u;
}

// =====================================================================
// Kernel 1: scores v2. Grid = (B, 16 qt) = 256 CTAs. Q resident; loop
// over 16 kt tiles with 2-stage cp.async K double-buffer. Mainloop and
// staged epilogue identical to round 13 per tile.
// =====================================================================
#define S_SMEM (3 * 128 * QLD_ * 2 + 128 * CLD_ * 4)   // 172032 B

__global__ __launch_bounds__(256, 1) void scores_mma(
    const float* __restrict__ mask, float* __restrict__ attn)
{
    extern __shared__ half sm[];
    half* Qh = sm;
    float* Cs = (float*)(sm + 3 * 128 * QLD_);

    const int b  = blockIdx.x;
    const int qt = blockIdx.y * 128;

    const half* qsrc = g_qh + ((size_t)b * S_ + qt) * D_;
    const half* ksrc = g_kh + (size_t)b * S_ * D_;

    const int tid  = threadIdx.x;
    const int wid  = tid >> 5, lane = tid & 31;
    const int g    = lane >> 2, c = lane & 3;
    const int wm   = (wid & 1) * 64;
    const int wn   = (wid >> 1) * 32;

    const uint32_t qbase = smem_u32(Qh);
    const uint32_t kb0   = qbase + 128 * QLD_ * 2;
    const uint32_t kb1   = qbase + 2 * 128 * QLD_ * 2;
    const int l15 = lane & 15;
    const int khi = (lane >> 4) << 3;

    // fill coords: 2048 16B chunks per 128x128-half tile, 8 per thread
    int frow[8], fc16[8];
#pragma unroll
    for (int t = 0; t < 8; t++) {
        const int idx = tid + t * 256;
        frow[t] = idx >> 4;
        fc16[t] = idx & 15;
    }

    // prologue: Q + K tile 0 (group 0), K tile 1 (group 1)
#pragma unroll
    for (int t = 0; t < 8; t++) {
        CPA16(qbase + (uint32_t)(frow[t] * QLD_ * 2 + fc16[t] * 16),
              qsrc + (size_t)frow[t] * D_ + fc16[t] * 8);
        CPA16(kb0 + (uint32_t)(frow[t] * QLD_ * 2 + fc16[t] * 16),
              ksrc + (size_t)frow[t] * D_ + fc16[t] * 8);
    }
    CP_COMMIT();
#pragma unroll
    for (int t = 0; t < 8; t++)
        CPA16(kb1 + (uint32_t)(frow[t] * QLD_ * 2 + fc16[t] * 16),
              ksrc + (size_t)(128 + frow[t]) * D_ + fc16[t] * 8);
    CP_COMMIT();

#pragma unroll 1
    for (int kt = 0; kt < 16; kt++) {
        CP_WAIT1();            // K tile kt (and Q) resident
        __syncthreads();       // also: prev tile's Cs reads complete

        float acc[4][4][4];
#pragma unroll
        for (int mi = 0; mi < 4; mi++)
#pragma unroll
            for (int ni = 0; ni < 4; ni++)
#pragma unroll
                for (int r = 0; r < 4; r++) acc[mi][ni][r] = 0.0f;

        const uint32_t kbase = (kt & 1) ? kb1 : kb0;

        // barrier-free mainloop (round-13 exact)
#pragma unroll
        for (int kq = 0; kq < 8; kq++) {
            const int koff = kq * 16 + khi;
            uint32_t b0[4], b1[4];
#pragma unroll
            for (int bg = 0; bg < 2; bg++) {
                const uint32_t a = kbase +
                    (uint32_t)(((wn + bg * 16 + l15) * QLD_ + koff) << 1);
                LDSM4(b0[2 * bg], b0[2 * bg + 1], b1[2 * bg], b1[2 * bg + 1], a);
            }
#pragma unroll
            for (int mi = 0; mi < 4; mi++) {
                uint32_t a0, a1, a2, a3;
                const uint32_t a = qbase +
                    (uint32_t)(((wm + mi * 16 + l15) * QLD_ + koff) << 1);
                LDSM4(a0, a1, a2, a3, a);
#pragma unroll
                for (int ni = 0; ni < 4; ni++)
                    mma16(acc[mi][ni], a0, a1, a2, a3, b0[ni], b1[ni]);
            }
        }
        __syncthreads();       // K buffer consumed -> refill allowed

        if (kt + 2 < 16) {
#pragma unroll
            for (int t = 0; t < 8; t++)
                CPA16(kbase + (uint32_t)(frow[t] * QLD_ * 2 + fc16[t] * 16),
                      ksrc + (size_t)((kt + 2) * 128 + frow[t]) * D_ + fc16[t] * 8);
        }
        CP_COMMIT();

        // staged epilogue (round-13 exact)
#pragma unroll
        for (int mi = 0; mi < 4; mi++) {
#pragma unroll
            for (int rr = 0; rr < 2; rr++) {
                const int row = wm + mi * 16 + g + rr * 8;
#pragma unroll
                for (int ni = 0; ni < 4; ni++) {
                    const int col = wn + ni * 8 + c * 2;
                    *(float2*)&Cs[row * CLD_ + col] =
                        make_float2(acc[mi][ni][rr * 2 + 0], acc[mi][ni][rr * 2 + 1]);
                }
            }
        }
        __syncthreads();

        const int lane4 = lane * 4;
        const int kcol  = kt * 128;
#pragma unroll
        for (int j = 0; j < 16; j++) {
            const int row = wid * 16 + j;
            const float4 cv = *(const float4*)&Cs[row * CLD_ + lane4];
            const float4 m4 = *(const float4*)&mask[(size_t)(qt + row) * S_ + kcol + lane4];
            float4 o;
            o.x = cv.x * SCALE_ + m4.x;
            o.y = cv.y * SCALE_ + m4.y;
            o.z = cv.z * SCALE_ + m4.z;
            o.w = cv.w * SCALE_ + m4.w;
            *(float4*)&attn[((size_t)b * S_ + qt + row) * S_ + kcol + lane4] = o;
        }
    }
}

// =====================================================================
// Kernel 2: row softmax (round-16 exact): fp32 in place + perm-packed
// half copy. Warp-shuffle reductions.
// =====================================================================
__global__ __launch_bounds__(256) void softmax_kernel(float* __restrict__ attn)
{
    __shared__ float redm[8], reds[8];
    const size_t row = blockIdx.x;
    float* p = attn + row * (size_t)S_;
    half* ph = g_phalf + row * (size_t)S_;
    const int tid = threadIdx.x;
    const int wid = tid >> 5, lane = tid & 31;

    float4 v0 = ((const float4*)p)[tid];
    float4 v1 = ((const float4*)p)[tid + 256];

    float m = fmaxf(fmaxf(fmaxf(v0.x, v0.y), fmaxf(v0.z, v0.w)),
                    fmaxf(fmaxf(v1.x, v1.y), fmaxf(v1.z, v1.w)));
#pragma unroll
    for (int o = 16; o > 0; o >>= 1)
        m = fmaxf(m, __shfl_xor_sync(0xFFFFFFFF, m, o));
    if (lane == 0) redm[wid] = m;
    __syncthreads();
    m = fmaxf(fmaxf(fmaxf(redm[0], redm[1]), fmaxf(redm[2], redm[3])),
              fmaxf(fmaxf(redm[4], redm[5]), fmaxf(redm[6], redm[7])));

    v0.x = __expf(v0.x - m); v0.y = __expf(v0.y - m);
    v0.z = __expf(v0.z - m); v0.w = __expf(v0.w - m);
    v1.x = __expf(v1.x - m); v1.y = __expf(v1.y - m);
    v1.z = __expf(v1.z - m); v1.w = __expf(v1.w - m);

    float s = (v0.x + v0.y) + (v0.z + v0.w) + (v1.x + v1.y) + (v1.z + v1.w);
#pragma unroll
    for (int o = 16; o > 0; o >>= 1)
        s += __shfl_xor_sync(0xFFFFFFFF, s, o);
    if (lane == 0) reds[wid] = s;
    __syncthreads();
    const float inv = 1.0f / (((reds[0] + reds[1]) + (reds[2] + reds[3])) +
                              ((reds[4] + reds[5]) + (reds[6] + reds[7])));

    v0.x *= inv; v0.y *= inv; v0.z *= inv; v0.w *= inv;
    v1.x *= inv; v1.y *= inv; v1.z *= inv; v1.w *= inv;
    ((float4*)p)[tid]       = v0;
    ((float4*)p)[tid + 256] = v1;

    store_perm(ph, tid * 4, v0);
    store_perm(ph, (tid + 256) * 4, v1);
}

// =====================================================================
// Kernel 3: out (round-16 exact): pure cp.async fills, double-buffered.
// =====================================================================
__global__ __launch_bounds__(256, 2) void out_mma(float* __restrict__ out)
{
    __shared__ half Ph2[2][128 * HLD_];
    __shared__ uint32_t Vs2[2][16 * VLD_];

    const int b  = blockIdx.x;
    const int qt = blockIdx.y * 128;

    const half* pb = g_phalf + ((size_t)b * S_ + qt) * S_;
    const uint32_t* vb = g_vpair + (size_t)b * (S_ / 2) * D_;

    const int tid  = threadIdx.x;
    const int wid  = tid >> 5, lane = tid & 31;
    const int g    = lane >> 2, c = lane & 3;
    const int wm   = (wid & 1) * 64;
    const int wn   = (wid >> 1) * 32;

    const uint32_t phb = smem_u32(Ph2);
    const uint32_t vsb = smem_u32(Vs2);

    float acc[4][4][4];
#pragma unroll
    for (int mi = 0; mi < 4; mi++)
#pragma unroll
        for (int ni = 0; ni < 4; ni++)
#pragma unroll
            for (int r = 0; r < 4; r++) acc[mi][ni][r] = 0.0f;

#pragma unroll
    for (int ch = 0; ch < 2; ch++) {
        const int k0 = ch * 32;
        const uint32_t pdst = phb + (uint32_t)ch * (128 * HLD_ * 2);
        const uint32_t vdst = vsb + (uint32_t)ch * (16 * VLD_ * 4);
#pragma unroll
        for (int t = 0; t < 2; t++) {
            const int idx = tid + t * 256;
            const int prow = idx >> 2, pc16 = idx & 3;
            CPA16(pdst + (uint32_t)(prow * HLD_ * 2 + pc16 * 16),
                  pb + (size_t)prow * S_ + k0 + pc16 * 8);
            const int vrow = idx >> 5, vc16 = idx & 31;
            CPA16(vdst + (uint32_t)(vrow * VLD_ * 4 + vc16 * 16),
                  vb + (size_t)(k0 / 2 + vrow) * D_ + vc16 * 4);
        }
        CP_COMMIT();
    }

#pragma unroll 1
    for (int s = 0; s < 64; s++) {
        CP_WAIT1();
        __syncthreads();

        const half* Ph = Ph2[s & 1];
        const uint32_t* Vs = Vs2[s & 1];
#pragma unroll
        for (int kq = 0; kq < 2; kq++) {
            const int co = kq * 16 + 4 * c;
            uint32_t bf[4][2];
#pragma unroll
            for (int ni = 0; ni < 4; ni++) {
                const int col = wn + ni * 8 + g;
                bf[ni][0] = Vs[(kq * 8 + c)     * VLD_ + col];
                bf[ni][1] = Vs[(kq * 8 + c + 4) * VLD_ + col];
            }
#pragma unroll
            for (int mi = 0; mi < 4; mi++) {
                const int row = wm + mi * 16 + g;
                const uint2 alo = *(const uint2*)&Ph[row * HLD_ + co];
                const uint2 ahi = *(const uint2*)&Ph[(row + 8) * HLD_ + co];
#pragma unroll
                for (int ni = 0; ni < 4; ni++)
                    mma16(acc[mi][ni], alo.x, ahi.x, alo.y, ahi.y, bf[ni][0], bf[ni][1]);
            }
        }
        __syncthreads();

        if (s + 2 < 64) {
            const int k0 = (s + 2) * 32;
            const uint32_t pdst = phb + (uint32_t)(s & 1) * (128 * HLD_ * 2);
            const uint32_t vdst = vsb + (uint32_t)(s & 1) * (16 * VLD_ * 4);
#pragma unroll
            for (int t = 0; t < 2; t++) {
                const int idx = tid + t * 256;
                const int prow = idx >> 2, pc16 = idx & 3;
                CPA16(pdst + (uint32_t)(prow * HLD_ * 2 + pc16 * 16),
                      pb + (size_t)prow * S_ + k0 + pc16 * 8);
                const int vrow = idx >> 5, vc16 = idx & 31;
                CPA16(vdst + (uint32_t)(vrow * VLD_ * 4 + vc16 * 16),
                      vb + (size_t)(k0 / 2 + vrow) * D_ + vc16 * 4);
            }
        }
        CP_COMMIT();
    }

#pragma unroll
    for (int mi = 0; mi < 4; mi++) {
#pragma unroll
        for (int rr = 0; rr < 2; rr++) {
            const int qrow = qt + wm + mi * 16 + g + rr * 8;
            float* orow = out + ((size_t)b * S_ + qrow) * D_;
#pragma unroll
            for (int ni = 0; ni < 4; ni++) {
                const int col = wn + ni * 8 + c * 2;
                float2 o = { acc[mi][ni][rr * 2 + 0], acc[mi][ni][rr * 2 + 1] };
                *(float2*)&orow[col] = o;
            }
        }
    }
}

// =====================================================================
// d_out = [output (B*S*D) | attn (B*S*S)]
// =====================================================================
extern "C" void kernel_launch(void* const* d_in, const int* in_sizes, int n_in,
                              void* d_out, int out_size)
{
    const float* q    = (const float*)d_in[0];
    const float* k    = (const float*)d_in[1];
    const float* v    = (const float*)d_in[2];
    const float* mask = (const float*)d_in[3];

    float* out  = (float*)d_out;
    float* attn = out + (size_t)B_ * S_ * D_;

    cudaFuncSetAttribute(scores_mma, cudaFuncAttributeMaxDynamicSharedMemorySize, S_SMEM);

    half* qh; cudaGetSymbolAddress((void**)&qh, g_qh);
    half* kh; cudaGetSymbolAddress((void**)&kh, g_kh);
    hprep_kernel<<<2048, 256>>>(q, qh);
    hprep_kernel<<<2048, 256>>>(k, kh);
    vprep_kernel<<<2048, 256>>>(v);

    dim3 g1(B_, S_ / 128);             // 16 x 16 = 256 CTAs
    scores_mma<<<g1, 256, S_SMEM>>>(mask, attn);

    softmax_kernel<<<B_ * S_, 256>>>(attn);

    dim3 g3(B_, S_ / 128);
    out_mma<<<g3, 256>>>(out);
}